// round 3
// baseline (speedup 1.0000x reference)
#include <cuda_runtime.h>

#define HW   4096
#define C    128
#define CR   32
#define G    8
#define CG   16
#define KK   49
#define KKG  392
#define NPX  16384   // B * H * W = 4 * 64 * 64

// Scratch (allocation-free: static __device__ arrays)
__device__ float g_red[CR * NPX];          // [32][16384] out-major, 2 MB
__device__ float g_ker[4 * KKG * HW];      // [B][392][HW], 25.7 MB

// ---------------------------------------------------------------------------
// Kernel 1: red[o][px] = sum_c x[b,c,hw] * w_reduce[o,c] + b_reduce[o]
// Block: 128 px tile, N=32 full, K=128. 256 thr, thread tile 4px x 4out.
// ---------------------------------------------------------------------------
__global__ __launch_bounds__(256) void k_reduce(const float* __restrict__ x,
                                                const float* __restrict__ wr,
                                                const float* __restrict__ br) {
    __shared__ float ws[C][CR + 1];   // [k][o], padded
    __shared__ float xs[16][128];     // [k_chunk][px]
    const int tid = threadIdx.x;
    const int px0 = blockIdx.x * 128;
    const int b   = px0 >> 12;
    const int hw0 = px0 & 4095;
    const float* xb = x + (size_t)b * C * HW + hw0;

    // stage w_reduce transposed (once)
    for (int idx = tid; idx < C * CR; idx += 256)
        ws[idx & 127][idx >> 7] = wr[idx];

    const int pg = tid & 31;        // px group (lane)
    const int og = tid >> 5;        // out group 0..7
    float acc[4][4] = {};

    for (int kc = 0; kc < C; kc += 16) {
        __syncthreads();
#pragma unroll
        for (int l = 0; l < 8; l++) {
            int idx = tid + l * 256;                    // 2048 elems
            xs[idx >> 7][idx & 127] = xb[(size_t)(kc + (idx >> 7)) * HW + (idx & 127)];
        }
        __syncthreads();
#pragma unroll
        for (int kk = 0; kk < 16; kk++) {
            float a[4], bb[4];
#pragma unroll
            for (int i = 0; i < 4; i++) a[i] = xs[kk][pg + 32 * i];
#pragma unroll
            for (int j = 0; j < 4; j++) bb[j] = ws[kc + kk][og + 8 * j];
#pragma unroll
            for (int i = 0; i < 4; i++)
#pragma unroll
                for (int j = 0; j < 4; j++)
                    acc[i][j] += a[i] * bb[j];
        }
    }
#pragma unroll
    for (int j = 0; j < 4; j++) {
        const int o = og + 8 * j;
        const float bj = br[o];
#pragma unroll
        for (int i = 0; i < 4; i++)
            g_red[o * NPX + px0 + pg + 32 * i] = acc[i][j] + bj;
    }
}

// ---------------------------------------------------------------------------
// Kernel 2: ker[b, o, hw] = sum_k red[k][px] * w_span[o, k] + b_span[o]
// Grid (128 px-tiles, 8 out-tiles of 49). 224 thr, thread tile 4px x 7out.
// ---------------------------------------------------------------------------
__global__ __launch_bounds__(224) void k_span(const float* __restrict__ wsg,
                                              const float* __restrict__ bs) {
    __shared__ float rs[CR][128];       // [k][px]
    __shared__ float wts[KK * CR];      // [o_local][k]
    const int tid = threadIdx.x;
    const int px0 = blockIdx.x * 128;
    const int ot  = blockIdx.y;         // 0..7
    const int b   = px0 >> 12;
    const int hw0 = px0 & 4095;

    for (int idx = tid; idx < CR * 128; idx += 224)
        rs[idx >> 7][idx & 127] = g_red[(idx >> 7) * NPX + px0 + (idx & 127)];
    for (int idx = tid; idx < KK * CR; idx += 224)
        wts[idx] = wsg[ot * KK * CR + idx];
    __syncthreads();

    const int pg = tid & 31;        // lane = px group
    const int og = tid >> 5;        // 0..6, warp-uniform
    float acc[4][7] = {};

#pragma unroll
    for (int k = 0; k < CR; k++) {
        float a[4], bb[7];
#pragma unroll
        for (int i = 0; i < 4; i++) a[i] = rs[k][pg + 32 * i];
#pragma unroll
        for (int j = 0; j < 7; j++) bb[j] = wts[(og * 7 + j) * CR + k];
#pragma unroll
        for (int i = 0; i < 4; i++)
#pragma unroll
            for (int j = 0; j < 7; j++)
                acc[i][j] += a[i] * bb[j];
    }
#pragma unroll
    for (int j = 0; j < 7; j++) {
        const int o = ot * KK + og * 7 + j;
        const float bj = bs[o];
        float* kp = g_ker + ((size_t)b * KKG + o) * HW + hw0;
#pragma unroll
        for (int i = 0; i < 4; i++)
            kp[pg + 32 * i] = acc[i][j] + bj;
    }
}

// ---------------------------------------------------------------------------
// Kernel 3: involution. Block = 16x16 spatial tile for one (b, g).
// Each thread owns one output pixel; its 49 kernel values live in registers
// and are reused across the 16 group channels. x patch staged per channel.
// out[b, g*16+c, h, w] = sum_{i,j} x[b, g*16+c, h+2i-6, w+2j-6] * ker[i*7+j]
// Patch needed: rows ty0-6 .. ty0+21 -> 28x28, row stride 48 so the two
// half-warps (consecutive ty) hit disjoint bank halves (48 = 16 mod 32).
// ---------------------------------------------------------------------------
__global__ __launch_bounds__(256) void k_inv(const float* __restrict__ x,
                                             float* __restrict__ out) {
    __shared__ float xs[28 * 48];      // 28x28 patch, row stride 48
    const int tx = threadIdx.x, ty = threadIdx.y;
    const int tid = ty * 16 + tx;
    const int tx0 = blockIdx.x * 16, ty0 = blockIdx.y * 16;
    const int bg = blockIdx.z;
    const int b = bg >> 3, g = bg & 7;
    const int pix = (ty0 + ty) * 64 + tx0 + tx;

    // per-pixel dynamic kernel -> registers (coalesced across tx)
    const float* kb = g_ker + ((size_t)b * KKG + g * KK) * HW + pix;
    float kreg[49];
#pragma unroll
    for (int kk = 0; kk < 49; kk++) kreg[kk] = kb[(size_t)kk * HW];

    const float* xb = x + ((size_t)b * C + g * CG) * HW;
    float* ob = out + ((size_t)b * C + g * CG) * HW + pix;

    for (int c = 0; c < CG; c++) {
        __syncthreads();
        const float* xc = xb + (size_t)c * HW;
#pragma unroll
        for (int l = 0; l < 4; l++) {
            int idx = tid + l * 256;
            if (idx < 28 * 28) {
                int r  = idx / 28;
                int cc = idx - r * 28;
                int gy = ty0 - 6 + r;
                int gx = tx0 - 6 + cc;
                float v = 0.f;
                if (gy >= 0 && gy < 64 && gx >= 0 && gx < 64)
                    v = xc[gy * 64 + gx];
                xs[r * 48 + cc] = v;
            }
        }
        __syncthreads();
        float acc = 0.f;
#pragma unroll
        for (int i = 0; i < 7; i++)
#pragma unroll
            for (int j = 0; j < 7; j++)
                acc += xs[(ty + 2 * i) * 48 + tx + 2 * j] * kreg[i * 7 + j];
        ob[(size_t)c * HW] = acc;
    }
}

// ---------------------------------------------------------------------------
extern "C" void kernel_launch(void* const* d_in, const int* in_sizes, int n_in,
                              void* d_out, int out_size) {
    const float* x  = (const float*)d_in[0];   // [4,128,64,64]
    const float* wr = (const float*)d_in[1];   // [32,128]
    const float* br = (const float*)d_in[2];   // [32]
    const float* wsp= (const float*)d_in[3];   // [392,32]
    const float* bsp= (const float*)d_in[4];   // [392]
    float* out = (float*)d_out;

    k_reduce<<<128, 256>>>(x, wr, br);
    k_span<<<dim3(128, 8), 224>>>(wsp, bsp);
    k_inv<<<dim3(4, 4, 32), dim3(16, 16)>>>(x, out);
}

// round 5
// speedup vs baseline: 1.4429x; 1.4429x over previous
#include <cuda_runtime.h>

#define HW   4096
#define C    128
#define CR   32
#define G    8
#define CG   16
#define KK   49
#define KKG  392
#define NPX  16384   // B * H * W

typedef unsigned long long u64;

// ---- packed f32x2 helpers (sm_103a) ---------------------------------------
__device__ __forceinline__ u64 pack2(float x, float y) {
    u64 r; asm("mov.b64 %0, {%1, %2};" : "=l"(r) : "f"(x), "f"(y)); return r;
}
__device__ __forceinline__ void unpack2(u64 v, float& x, float& y) {
    asm("mov.b64 {%0, %1}, %2;" : "=f"(x), "=f"(y) : "l"(v));
}
__device__ __forceinline__ void ffma2(u64& d, u64 a, u64 b) {
    asm("fma.rn.f32x2 %0, %1, %2, %0;" : "+l"(d) : "l"(a), "l"(b));
}

// Scratch (16B-aligned: we do float2/u64 accesses into these)
__device__ __align__(16) float g_red[NPX * CR];        // [px][32]
__device__ __align__(16) float g_ker[4 * KKG * HW];    // [b][392][hw]

// ---------------------------------------------------------------------------
// Kernel 1: red[px][o] = sum_c x[b,c,hw] * w_reduce[o,c] + b_reduce[o]
// lane = out (32 outs = warp). w chunk in registers, x broadcast LDS.128.
// Block 256 thr (8 warps x 8 px) -> 64 px/block. Grid 256.
// ---------------------------------------------------------------------------
__global__ __launch_bounds__(256) void k_reduce(const float* __restrict__ x,
                                                const float* __restrict__ wr,
                                                const float* __restrict__ br) {
    __shared__ float wsT[C][CR + 2];   // [c][o], pad 34 (even -> rows 8B-aligned)
    __shared__ float xs[32][64];       // [k][px]
    const int tid  = threadIdx.x;
    const int lane = tid & 31;         // = out channel
    const int warp = tid >> 5;
    const int pxw  = warp * 8;         // warp's px base within tile
    const int px0  = blockIdx.x * 64;
    const int b    = px0 >> 12;
    const int hw0  = px0 & 4095;
    const float* xb = x + (size_t)b * C * HW + hw0;

    // stage w_reduce transposed once: wsT[c][o]
#pragma unroll
    for (int l = 0; l < 16; l++) {
        int idx = tid + l * 256;                  // 4096 = 32*128
        wsT[idx & 127][idx >> 7] = wr[idx];
    }

    u64 acc[4] = {0, 0, 0, 0};

    for (int kc = 0; kc < C; kc += 32) {
        __syncthreads();
#pragma unroll
        for (int l = 0; l < 8; l++) {
            int idx = tid + l * 256;              // 2048 = 32*64
            xs[idx >> 6][idx & 63] = xb[(size_t)(kc + (idx >> 6)) * HW + (idx & 63)];
        }
        __syncthreads();

        float breg[32];
#pragma unroll
        for (int k = 0; k < 32; k++) breg[k] = wsT[kc + k][lane];

#pragma unroll
        for (int k = 0; k < 32; k++) {
            const float4 v0 = *(const float4*)&xs[k][pxw];      // px 0..3 (uniform bcast)
            const float4 v1 = *(const float4*)&xs[k][pxw + 4];  // px 4..7
            const u64 b2 = pack2(breg[k], breg[k]);
            ffma2(acc[0], pack2(v0.x, v0.y), b2);
            ffma2(acc[1], pack2(v0.z, v0.w), b2);
            ffma2(acc[2], pack2(v1.x, v1.y), b2);
            ffma2(acc[3], pack2(v1.z, v1.w), b2);
        }
    }

    const float bias = br[lane];
#pragma unroll
    for (int p = 0; p < 4; p++) {
        float f0, f1; unpack2(acc[p], f0, f1);
        g_red[(px0 + pxw + 2 * p + 0) * 32 + lane] = f0 + bias;   // coalesced 128B
        g_red[(px0 + pxw + 2 * p + 1) * 32 + lane] = f1 + bias;
    }
}

// ---------------------------------------------------------------------------
// Kernel 2: ker[b][o][hw] = sum_k red[px][k] * w_span[o][k] + b_span[o]
// Rank-1 tiles: 256 px x 56 outs per block (8 warps x 7 outs, 8 px/lane).
// Grid (64, 7). f32x2 math. K=32 fully unrolled.
// ---------------------------------------------------------------------------
__global__ __launch_bounds__(256) void k_span(const float* __restrict__ wsp,
                                              const float* __restrict__ bs) {
    __shared__ float rs[CR][258];      // [k][px], pad 258 (EVEN: rows 8B-aligned)
    __shared__ float ws[56 * 32];      // [o_local][k]
    const int tid  = threadIdx.x;
    const int lane = tid & 31;
    const int warp = tid >> 5;
    const int px0  = blockIdx.x * 256;
    const int o0   = blockIdx.y * 56;
    const int b    = px0 >> 12;
    const int hw0  = px0 & 4095;

    // stage red tile, transposing [px][k] -> rs[k][px]
#pragma unroll
    for (int l = 0; l < 32; l++) {
        int idx = tid + l * 256;                  // 8192 = 256*32
        int px = idx >> 5, k = idx & 31;
        rs[k][px] = g_red[(px0 + px) * 32 + k];   // 128B coalesced reads
    }
#pragma unroll
    for (int l = 0; l < 7; l++) {
        int idx = tid + l * 256;                  // 1792 = 56*32
        ws[idx] = wsp[o0 * 32 + idx];
    }
    __syncthreads();

    u64 acc[4][7] = {};

#pragma unroll
    for (int k = 0; k < 32; k++) {
        u64 a[4];
#pragma unroll
        for (int v = 0; v < 4; v++)
            a[v] = *(const u64*)&rs[k][2 * lane + 64 * v];
#pragma unroll
        for (int j = 0; j < 7; j++) {
            const float bv = ws[(warp * 7 + j) * 32 + k];   // uniform bcast
            const u64 b2 = pack2(bv, bv);
#pragma unroll
            for (int v = 0; v < 4; v++) ffma2(acc[v][j], a[v], b2);
        }
    }

#pragma unroll
    for (int j = 0; j < 7; j++) {
        const int o = o0 + warp * 7 + j;
        const float bias = bs[o];
        float* kp = g_ker + ((size_t)b * KKG + o) * HW + hw0;
#pragma unroll
        for (int v = 0; v < 4; v++) {
            float f0, f1; unpack2(acc[v][j], f0, f1);
            *(float2*)&kp[2 * lane + 64 * v] = make_float2(f0 + bias, f1 + bias);
        }
    }
}

// ---------------------------------------------------------------------------
// Kernel 3: involution. Block = 32x16 spatial tile for one (b, g).
// Thread owns 2 horizontal px: taps are adjacent floats -> 1 LDS.64 + 1 FFMA2
// per tap serves both. 49 dynamic-kernel f32x2 in regs, reused over 16 ch.
// 4 channels staged per sync round.
// ---------------------------------------------------------------------------
__global__ __launch_bounds__(256) void k_inv(const float* __restrict__ x,
                                             float* __restrict__ out) {
    __shared__ float xs[4][28][48];    // 4 channels, 28x44 patch (stride 48: rows 8B-aligned)
    const int tx = threadIdx.x, ty = threadIdx.y;   // (16,16)
    const int tid = ty * 16 + tx;
    const int tx0 = blockIdx.x * 32, ty0 = blockIdx.y * 16;
    const int bg = blockIdx.z;
    const int b = bg >> 3, g = bg & 7;
    const int pix = (ty0 + ty) * 64 + tx0 + 2 * tx;   // even -> 8B aligned

    // 49 per-pixel kernel pairs -> registers (coalesced LDG.64)
    const float* kb = g_ker + ((size_t)b * KKG + g * KK) * HW + pix;
    u64 kreg[49];
#pragma unroll
    for (int kk = 0; kk < 49; kk++) kreg[kk] = *(const u64*)&kb[(size_t)kk * HW];

    const float* xb = x + ((size_t)b * C + g * CG) * HW;
    float* ob = out + ((size_t)b * C + g * CG) * HW + pix;

    for (int c0 = 0; c0 < CG; c0 += 4) {
        __syncthreads();
        // stage 4 channels: 28 rows x 44 cols each
#pragma unroll
        for (int cc = 0; cc < 4; cc++) {
            const float* xc = xb + (size_t)(c0 + cc) * HW;
#pragma unroll
            for (int l = 0; l < 5; l++) {
                int idx = tid + l * 256;
                if (idx < 28 * 44) {
                    int r  = idx / 44;
                    int ccol = idx - r * 44;
                    int gy = ty0 - 6 + r;
                    int gx = tx0 - 6 + ccol;
                    float v = 0.f;
                    if (gy >= 0 && gy < 64 && gx >= 0 && gx < 64)
                        v = xc[gy * 64 + gx];
                    xs[cc][r][ccol] = v;
                }
            }
        }
        __syncthreads();

#pragma unroll
        for (int cc = 0; cc < 4; cc++) {
            u64 acc = 0;
#pragma unroll
            for (int i = 0; i < 7; i++)
#pragma unroll
                for (int j = 0; j < 7; j++) {
                    const u64 v = *(const u64*)&xs[cc][ty + 2 * i][2 * tx + 2 * j];
                    ffma2(acc, v, kreg[i * 7 + j]);
                }
            float f0, f1; unpack2(acc, f0, f1);
            *(float2*)&ob[(size_t)(c0 + cc) * HW] = make_float2(f0, f1);
        }
    }
}

// ---------------------------------------------------------------------------
extern "C" void kernel_launch(void* const* d_in, const int* in_sizes, int n_in,
                              void* d_out, int out_size) {
    const float* x   = (const float*)d_in[0];   // [4,128,64,64]
    const float* wr  = (const float*)d_in[1];   // [32,128]
    const float* br  = (const float*)d_in[2];   // [32]
    const float* wsp = (const float*)d_in[3];   // [392,32]
    const float* bsp = (const float*)d_in[4];   // [392]
    float* out = (float*)d_out;

    k_reduce<<<256, 256>>>(x, wr, br);
    k_span<<<dim3(64, 7), 256>>>(wsp, bsp);
    k_inv<<<dim3(2, 4, 32), dim3(16, 16)>>>(x, out);
}